// round 3
// baseline (speedup 1.0000x reference)
#include <cuda_runtime.h>
#include <cuda_bf16.h>
#include <cstdint>

// DomainCalibratedLoss:
//   loss_i = logsumexp_j( x[i,j] + log w[d_i, j] ) - ( x[i,t_i] + log w[d_i, t_i] )
//   out    = sum_i valid_i * loss_i / N
//
// N = 500000, C = 200 classes, D = 8 domains.
// HBM-bound: 400MB of inputs streamed once (never reused) -> __ldcs streaming
// loads. One warp per point, float4 loads, smem log-weight table, shuffle LSE.

#define N_CLASSES 200
#define N_DOMAINS 8
#define NVEC 50            // float4 vectors per row (200/4)
#define IGNORE_LBL 255

__device__ int g_idx64_flag;   // 1 if targets/domains are int64, 0 if int32

// ---------------------------------------------------------------------------
// Pre-kernel: detect index dtype + zero the output scalar.
// int32 data reinterpreted as int64 packs two labels per word -> values far
// outside [0,255] with overwhelming probability across 64 samples.
// ---------------------------------------------------------------------------
__global__ void dcl_detect_init(const void* __restrict__ targets, int n,
                                float* __restrict__ out) {
    if (blockIdx.x == 0 && threadIdx.x == 0) {
        const long long* t64 = (const long long*)targets;
        int ok = 1;
        int m = (n < 64) ? n : 64;
        for (int i = 0; i < m; ++i) {
            long long v = t64[i];
            if (v < 0 || v > 255) { ok = 0; break; }
        }
        g_idx64_flag = ok;
        out[0] = 0.0f;
    }
}

// ---------------------------------------------------------------------------
// Main kernel: one warp per point, grid-stride over points.
// ---------------------------------------------------------------------------
__global__ __launch_bounds__(256, 8)
void dcl_kernel(const float* __restrict__ x,
                const void*  __restrict__ tgt_raw,
                const void*  __restrict__ dom_raw,
                const float* __restrict__ w,
                float* __restrict__ out,
                int n) {
    __shared__ float slogw[N_DOMAINS * N_CLASSES];   // 6.4 KB

    // Precompute log(w). Weights are strictly positive in this problem;
    // guard w<=0 with -inf semantics via large negative.
    for (int i = threadIdx.x; i < N_DOMAINS * N_CLASSES; i += blockDim.x) {
        float wi = w[i];
        slogw[i] = (wi > 0.0f) ? __logf(wi) : -1e30f;
    }
    __syncthreads();

    const int idx64 = g_idx64_flag;
    const int lane  = threadIdx.x & 31;
    const int warp_global = blockIdx.x * (blockDim.x >> 5) + (threadIdx.x >> 5);
    const int nwarps      = gridDim.x * (blockDim.x >> 5);
    const unsigned FULL = 0xFFFFFFFFu;
    const float inv_n = 1.0f / (float)n;

    float acc = 0.0f;  // meaningful on lane 0 only

    for (int p = warp_global; p < n; p += nwarps) {
        int t, d;
        if (idx64) {
            t = (int)((const long long*)tgt_raw)[p];
            d = (int)((const long long*)dom_raw)[p];
        } else {
            t = ((const int*)tgt_raw)[p];
            d = ((const int*)dom_raw)[p];
        }
        const bool valid = (t != IGNORE_LBL);
        int tc = t;
        if (tc < 0) tc = 0;
        if (tc > N_CLASSES - 1) tc = N_CLASSES - 1;

        const float4* row = (const float4*)(x + (size_t)p * N_CLASSES);
        const float4* lw4 = (const float4*)(slogw + d * N_CLASSES);  // 800B-aligned

        // lane handles vector indices: lane (group 0), lane+32 (group 1, lanes 0..17)
        // __ldcs: streaming (evict-first) — each line touched exactly once.
        float4 a  = __ldcs(row + lane);
        float4 la = lw4[lane];
        float v0 = a.x + la.x, v1 = a.y + la.y, v2 = a.z + la.z, v3 = a.w + la.w;

        float v4 = -1e30f, v5 = -1e30f, v6 = -1e30f, v7 = -1e30f;
        const bool has2 = (lane < (NVEC - 32));   // lanes 0..17
        if (has2) {
            float4 b  = __ldcs(row + lane + 32);
            float4 lb = lw4[lane + 32];
            v4 = b.x + lb.x; v5 = b.y + lb.y; v6 = b.z + lb.z; v7 = b.w + lb.w;
        }

        // --- warp max ---
        float mx = fmaxf(fmaxf(fmaxf(v0, v1), fmaxf(v2, v3)),
                         fmaxf(fmaxf(v4, v5), fmaxf(v6, v7)));
        #pragma unroll
        for (int off = 16; off > 0; off >>= 1)
            mx = fmaxf(mx, __shfl_xor_sync(FULL, mx, off));

        // --- warp sum of exp(v - mx) ---
        float s = __expf(v0 - mx) + __expf(v1 - mx) +
                  __expf(v2 - mx) + __expf(v3 - mx);
        if (has2)
            s += __expf(v4 - mx) + __expf(v5 - mx) +
                 __expf(v6 - mx) + __expf(v7 - mx);
        #pragma unroll
        for (int off = 16; off > 0; off >>= 1)
            s += __shfl_xor_sync(FULL, s, off);

        const float lse = mx + __logf(s);

        // --- target score: owner lane = (tc>>2) & 31, group = tc>=128 ---
        const int vt = tc >> 2;          // vector index 0..49
        const int k  = tc & 3;           // element within float4 (warp-uniform)
        float c03  = (k == 0) ? v0 : (k == 1) ? v1 : (k == 2) ? v2 : v3;
        float c47  = (k == 0) ? v4 : (k == 1) ? v5 : (k == 2) ? v6 : v7;
        float cand = (vt < 32) ? c03 : c47;
        const float ts = __shfl_sync(FULL, cand, vt & 31);

        if (lane == 0 && valid) acc += (lse - ts);
    }

    // one atomic per warp, pre-scaled by 1/N
    if (lane == 0 && acc != 0.0f) {
        atomicAdd(out, acc * inv_n);
    }
}

extern "C" void kernel_launch(void* const* d_in, const int* in_sizes, int n_in,
                              void* d_out, int out_size) {
    const float* x   = (const float*)d_in[0];   // inputs  [N, 200] f32
    const void*  tgt = d_in[1];                 // targets [N] int32 or int64
    const void*  dom = d_in[2];                 // domains [N] int32 or int64
    const float* w   = (const float*)d_in[3];   // dcc_weights [8, 200] f32
    float* out = (float*)d_out;

    // Derive N from inputs' element count — dtype-unambiguous (f32 [N,200]).
    const int n = in_sizes[0] / N_CLASSES;

    dcl_detect_init<<<1, 32>>>(tgt, n, out);

    const int threads = 256;
    const int blocks  = 1184;                   // 148 SMs * 8 blocks
    dcl_kernel<<<blocks, threads>>>(x, tgt, dom, w, out, n);
}